// round 1
// baseline (speedup 1.0000x reference)
#include <cuda_runtime.h>

#define BB 16
#define NN 4096
#define CC 1024
#define HH 16
#define DD 64

// Persistent scratch (allocation-free rule: __device__ globals)
__device__ float g_watt[BB*HH*CC];    // folded attention weights  [b][h][c]
__device__ float g_att[BB*HH*NN];     // logits, then exp values   [b][h][n]
__device__ float g_denom[BB*HH];      // softmax denominators
__device__ float g_xa[BB*HH*CC];      // attn-weighted x           [b][h][c]
__device__ float g_cls[BB*CC];        // cls embedding             [b][h*64+d]

// ---------------------------------------------------------------------------
// Kernel 1: per (b,h) compute q = x[b,0,:] @ Wq[:,h,:] (scaled), then
// w_att[b,h,c] = sum_d Wkv_k[c,h,d] * q[d].   Tiny (33 MFLOP total).
// ---------------------------------------------------------------------------
__global__ void k_watt(const float* __restrict__ x,
                       const float* __restrict__ Wq,
                       const float* __restrict__ Wkv) {
    int b = blockIdx.x >> 4;
    int h = blockIdx.x & 15;
    int t = threadIdx.x;   // 256 threads
    __shared__ float xs[CC];
    __shared__ float qpart[256];
    __shared__ float qs[DD];

    const float* xrow = x + (size_t)b * NN * CC;   // token 0 of batch b
    for (int c = t; c < CC; c += 256) xs[c] = xrow[c];
    __syncthreads();

    // q[d]: 4 threads per d, each over a 256-wide c-chunk
    {
        int d = t >> 2, part = t & 3;
        const float* wq = Wq + h * DD + d;         // column h*64+d, row stride 1024
        float acc = 0.f;
        int c0 = part * 256;
        #pragma unroll 8
        for (int c = c0; c < c0 + 256; ++c)
            acc += xs[c] * wq[(size_t)c * (HH * DD)];
        qpart[t] = acc;
    }
    __syncthreads();
    if (t < DD) {
        float q = qpart[t*4] + qpart[t*4+1] + qpart[t*4+2] + qpart[t*4+3];
        qs[t] = q * 0.125f;   // scale = D^-0.5 = 1/8, folded into q
    }
    __syncthreads();

    // w_att[c] = sum_d Wkv[c, h*64+d] * qs[d]   (k-half: column offset h*64)
    for (int c = t; c < CC; c += 256) {
        const float4* wk = (const float4*)(Wkv + (size_t)c * (2*HH*DD) + h * DD);
        float s = 0.f;
        #pragma unroll
        for (int j4 = 0; j4 < DD/4; ++j4) {
            float4 w = wk[j4];
            s += w.x * qs[j4*4+0] + w.y * qs[j4*4+1]
               + w.z * qs[j4*4+2] + w.w * qs[j4*4+3];
        }
        g_watt[((size_t)b*HH + h)*CC + c] = s;
    }
}

// ---------------------------------------------------------------------------
// Kernel 2 (big pass 1): logits[b,h,n] = x[b,n,:] . w_att[b,h,:]
// Thread layout: hg = t&3 -> heads {hg, hg+4, hg+8, hg+12} (w_att in regs),
// sidx = t>>2 -> c-slice [sidx*16, sidx*16+16). Shuffle-reduce over c.
// ---------------------------------------------------------------------------
#define RPB 128
__global__ void __launch_bounds__(256) k_logits(const float* __restrict__ x) {
    int b      = blockIdx.y;
    int n_base = blockIdx.x * RPB;
    int t      = threadIdx.x;
    int hg     = t & 3;
    int sidx   = t >> 2;      // 0..63
    int lane   = t & 31;
    int w      = t >> 5;      // warp id 0..7

    __shared__ float s_red[4*8*16];   // [r][warp][head]

    // w_att for 4 heads x 16 c-values, held in registers
    float4 wr[4][4];
    #pragma unroll
    for (int g = 0; g < 4; ++g) {
        const float4* wp = (const float4*)(g_watt + ((size_t)b*HH + hg + 4*g)*CC + sidx*16);
        wr[g][0] = wp[0]; wr[g][1] = wp[1]; wr[g][2] = wp[2]; wr[g][3] = wp[3];
    }

    const float* xb = x + (size_t)b * NN * CC;
    for (int n0 = 0; n0 < RPB; n0 += 4) {
        float p[4][4];
        #pragma unroll
        for (int r = 0; r < 4; ++r) {
            int n = n_base + n0 + r;
            const float4* xp = (const float4*)(xb + (size_t)n*CC + sidx*16);
            #pragma unroll
            for (int g = 0; g < 4; ++g) p[r][g] = 0.f;
            #pragma unroll
            for (int q4 = 0; q4 < 4; ++q4) {
                float4 xv = xp[q4];
                #pragma unroll
                for (int g = 0; g < 4; ++g) {
                    float4 w4 = wr[g][q4];
                    p[r][g] += xv.x*w4.x + xv.y*w4.y + xv.z*w4.z + xv.w*w4.w;
                }
            }
        }
        // reduce over the 8 lanes sharing hg (c-slices within this warp)
        #pragma unroll
        for (int r = 0; r < 4; ++r)
            #pragma unroll
            for (int g = 0; g < 4; ++g) {
                float v = p[r][g];
                v += __shfl_xor_sync(0xffffffffu, v, 4);
                v += __shfl_xor_sync(0xffffffffu, v, 8);
                v += __shfl_xor_sync(0xffffffffu, v, 16);
                p[r][g] = v;
            }
        if (lane < 4) {
            #pragma unroll
            for (int r = 0; r < 4; ++r)
                #pragma unroll
                for (int g = 0; g < 4; ++g)
                    s_red[(r*8 + w)*16 + lane + 4*g] = p[r][g];
        }
        __syncthreads();
        if (t < 64) {
            int r = t >> 4, h = t & 15;
            float s = 0.f;
            #pragma unroll
            for (int ww = 0; ww < 8; ++ww) s += s_red[(r*8 + ww)*16 + h];
            g_att[((size_t)b*HH + h)*NN + n_base + n0 + r] = s;
        }
        __syncthreads();
    }
}

// ---------------------------------------------------------------------------
// Kernel 3: softmax over n for each (b,h) row; stores exp in place + denom.
// Also zeroes g_xa for this (b,h) — required for graph-replay determinism.
// ---------------------------------------------------------------------------
__global__ void k_softmax() {
    int bh = blockIdx.x;              // 0..255
    int t  = threadIdx.x;             // 256
    float* row = g_att + (size_t)bh * NN;
    __shared__ float sred[256];

    for (int i = t; i < CC; i += 256) g_xa[(size_t)bh*CC + i] = 0.f;

    float m = -1e30f;
    for (int i = t; i < NN; i += 256) m = fmaxf(m, row[i]);
    sred[t] = m; __syncthreads();
    for (int s = 128; s > 0; s >>= 1) {
        if (t < s) sred[t] = fmaxf(sred[t], sred[t+s]);
        __syncthreads();
    }
    m = sred[0]; __syncthreads();

    float sum = 0.f;
    for (int i = t; i < NN; i += 256) {
        float e = __expf(row[i] - m);
        row[i] = e;
        sum += e;
    }
    sred[t] = sum; __syncthreads();
    for (int s = 128; s > 0; s >>= 1) {
        if (t < s) sred[t] += sred[t+s];
        __syncthreads();
    }
    if (t == 0) g_denom[bh] = sred[0];
}

// ---------------------------------------------------------------------------
// Kernel 4 (big pass 2): xa[b,h,c] += sum_n p[b,h,n] * x[b,n,c]
// Same (hg, sidx) layout; 64 fp32 accumulators per thread; atomic epilogue.
// ---------------------------------------------------------------------------
#define RPB2 256
__global__ void __launch_bounds__(256) k_xa(const float* __restrict__ x) {
    int b      = blockIdx.y;
    int n_base = blockIdx.x * RPB2;
    int t      = threadIdx.x;
    int hg     = t & 3;
    int sidx   = t >> 2;

    __shared__ float ps[RPB2 * 16];   // [n_local][h]  (16 KB)
    {
        int h = t >> 4, chunk = t & 15;
        const float* arow = g_att + ((size_t)b*HH + h)*NN + n_base + chunk*16;
        #pragma unroll
        for (int i = 0; i < 16; ++i)
            ps[(chunk*16 + i)*16 + h] = arow[i];
    }
    __syncthreads();

    float acc[4][16];
    #pragma unroll
    for (int g = 0; g < 4; ++g)
        #pragma unroll
        for (int j = 0; j < 16; ++j) acc[g][j] = 0.f;

    const float* xb = x + ((size_t)b*NN + n_base)*CC + sidx*16;
    for (int nl = 0; nl < RPB2; ++nl) {
        const float4* xp = (const float4*)(xb + (size_t)nl * CC);
        float pv[4];
        #pragma unroll
        for (int g = 0; g < 4; ++g) pv[g] = ps[nl*16 + hg + 4*g];
        #pragma unroll
        for (int q4 = 0; q4 < 4; ++q4) {
            float4 xv = xp[q4];
            #pragma unroll
            for (int g = 0; g < 4; ++g) {
                acc[g][q4*4+0] += pv[g] * xv.x;
                acc[g][q4*4+1] += pv[g] * xv.y;
                acc[g][q4*4+2] += pv[g] * xv.z;
                acc[g][q4*4+3] += pv[g] * xv.w;
            }
        }
    }

    #pragma unroll
    for (int g = 0; g < 4; ++g) {
        float* dst = g_xa + ((size_t)b*HH + hg + 4*g)*CC + sidx*16;
        #pragma unroll
        for (int j = 0; j < 16; ++j) atomicAdd(dst + j, acc[g][j]);
    }
}

// ---------------------------------------------------------------------------
// Kernel 5: cls[b,h,d] = (1/denom) * sum_c xa[b,h,c] * Wkv_v[c,h,d]
// Also pre-initializes out with bproj (d_out is poisoned; k_proj atomic-adds).
// ---------------------------------------------------------------------------
__global__ void k_cls(const float* __restrict__ Wkv,
                      const float* __restrict__ bproj,
                      float* __restrict__ out) {
    int b = blockIdx.x >> 4, h = blockIdx.x & 15;
    int d = threadIdx.x;   // 64
    __shared__ float xas[CC];
    const float* xa = g_xa + ((size_t)b*HH + h)*CC;
    for (int c = d; c < CC; c += 64) xas[c] = xa[c];
    __syncthreads();

    const float* wv = Wkv + (HH*DD) + h*DD + d;   // v-half column offset 1024
    float acc = 0.f;
    #pragma unroll 8
    for (int c = 0; c < CC; ++c)
        acc += xas[c] * wv[(size_t)c * (2*HH*DD)];

    float inv = 1.0f / g_denom[b*HH + h];
    int col = h*DD + d;
    g_cls[(size_t)b*CC + col] = acc * inv;
    out[(size_t)b*CC + col]   = bproj[col];
}

// ---------------------------------------------------------------------------
// Kernel 6: out[b,j] += sum_i cls[b,i] * Wproj[i,j]   (i split across blocks)
// ---------------------------------------------------------------------------
__global__ void k_proj(const float* __restrict__ Wproj,
                       float* __restrict__ out) {
    int jc = blockIdx.x;   // 0..3
    int ic = blockIdx.y;   // 0..3
    int b  = blockIdx.z;   // 0..15
    int tt = threadIdx.x;  // 256
    int j  = jc*256 + tt;

    __shared__ float cs[256];
    cs[tt] = g_cls[(size_t)b*CC + ic*256 + tt];
    __syncthreads();

    const float* wp = Wproj + (size_t)(ic*256) * CC + j;
    float acc = 0.f;
    #pragma unroll 8
    for (int i = 0; i < 256; ++i)
        acc += cs[i] * wp[(size_t)i * CC];
    atomicAdd(&out[(size_t)b*CC + j], acc);
}

// ---------------------------------------------------------------------------
extern "C" void kernel_launch(void* const* d_in, const int* in_sizes, int n_in,
                              void* d_out, int out_size) {
    const float* x     = (const float*)d_in[0];
    const float* Wq    = (const float*)d_in[1];
    const float* Wkv   = (const float*)d_in[2];
    const float* Wproj = (const float*)d_in[3];
    const float* bproj = (const float*)d_in[4];
    float* out = (float*)d_out;

    k_watt   <<<BB*HH, 256>>>(x, Wq, Wkv);
    k_logits <<<dim3(NN/RPB, BB), 256>>>(x);
    k_softmax<<<BB*HH, 256>>>();
    k_xa     <<<dim3(NN/RPB2, BB), 256>>>(x);
    k_cls    <<<BB*HH, 64>>>(Wkv, bproj, out);
    k_proj   <<<dim3(4, 4, BB), 256>>>(Wproj, out);
}

// round 2
// speedup vs baseline: 1.2413x; 1.2413x over previous
#include <cuda_runtime.h>

#define BB 16
#define NN 4096
#define CC 1024
#define HH 16
#define DD 64

typedef unsigned long long u64;

__device__ __forceinline__ u64 pack2(float lo, float hi) {
    u64 r; asm("mov.b64 %0, {%1, %2};" : "=l"(r) : "f"(lo), "f"(hi)); return r;
}
__device__ __forceinline__ void unpack2(u64 v, float& lo, float& hi) {
    asm("mov.b64 {%0, %1}, %2;" : "=f"(lo), "=f"(hi) : "l"(v));
}
__device__ __forceinline__ void ffma2(u64& d, u64 a, u64 b) {
    asm("fma.rn.f32x2 %0, %1, %2, %0;" : "+l"(d) : "l"(a), "l"(b));
}

// Persistent scratch (allocation-free rule: __device__ globals)
__device__ float g_watt[BB*HH*CC];    // folded attention weights  [b][h][c]
__device__ float g_att[BB*HH*NN];     // logits, then exp values   [b][h][n]
__device__ float g_denom[BB*HH];      // softmax denominators
__device__ float g_xa[BB*HH*CC];      // attn-weighted x           [b][h][c]
__device__ float g_cls[BB*CC];        // cls embedding             [b][h*64+d]

// ---------------------------------------------------------------------------
// Kernel 1: per (b,h): q = scale * x[b,0,:] @ Wq[:,h,:]; then
// w_att[b,h,c] = sum_d Wkv_k[c,h,d] * q[d].
// ---------------------------------------------------------------------------
__global__ void k_watt(const float* __restrict__ x,
                       const float* __restrict__ Wq,
                       const float* __restrict__ Wkv) {
    int b = blockIdx.x >> 4;
    int h = blockIdx.x & 15;
    int t = threadIdx.x;   // 256 threads
    __shared__ float xs[CC];
    __shared__ float qpart[256];
    __shared__ float qs[DD];

    const float* xrow = x + (size_t)b * NN * CC;   // token 0 of batch b
    for (int c = t; c < CC; c += 256) xs[c] = xrow[c];
    __syncthreads();

    {
        int d = t >> 2, part = t & 3;
        const float* wq = Wq + h * DD + d;
        float acc = 0.f;
        int c0 = part * 256;
        #pragma unroll 8
        for (int c = c0; c < c0 + 256; ++c)
            acc += xs[c] * wq[(size_t)c * (HH * DD)];
        qpart[t] = acc;
    }
    __syncthreads();
    if (t < DD) {
        float q = qpart[t*4] + qpart[t*4+1] + qpart[t*4+2] + qpart[t*4+3];
        qs[t] = q * 0.125f;   // scale = D^-0.5 = 1/8
    }
    __syncthreads();

    for (int c = t; c < CC; c += 256) {
        const float4* wk = (const float4*)(Wkv + (size_t)c * (2*HH*DD) + h * DD);
        float s = 0.f;
        #pragma unroll
        for (int j4 = 0; j4 < DD/4; ++j4) {
            float4 w = wk[j4];
            s += w.x * qs[j4*4+0] + w.y * qs[j4*4+1]
               + w.z * qs[j4*4+2] + w.w * qs[j4*4+3];
        }
        g_watt[((size_t)b*HH + h)*CC + c] = s;
    }
}

// ---------------------------------------------------------------------------
// Kernel 2 (big pass 1): logits[b,h,n] = x[b,n,:] . w_att[b,h,:]
// hg = t&3 -> heads {hg, hg+4, hg+8, hg+12} (w_att in packed regs),
// sidx = t>>2 -> 16-float c-slice. Packed f32x2 FMAs; shuffle+smem reduce.
// ---------------------------------------------------------------------------
#define LR 64
__global__ void __launch_bounds__(256, 2) k_logits(const float* __restrict__ x) {
    int b      = blockIdx.y;
    int n_base = blockIdx.x * LR;
    int t      = threadIdx.x;
    int hg     = t & 3;
    int sidx   = t >> 2;      // 0..63
    int lane   = t & 31;
    int w      = t >> 5;      // warp id 0..7

    __shared__ float s_red[4*8*16];   // [r][warp][head]

    // w_att for 4 heads x 16 c-values, packed (8 x f32x2 per head)
    u64 w2[4][8];
    #pragma unroll
    for (int g = 0; g < 4; ++g) {
        const ulonglong2* wp =
            (const ulonglong2*)(g_watt + ((size_t)b*HH + hg + 4*g)*CC + sidx*16);
        #pragma unroll
        for (int j = 0; j < 4; ++j) {
            ulonglong2 v = wp[j];
            w2[g][2*j]   = v.x;
            w2[g][2*j+1] = v.y;
        }
    }

    const float* xb = x + (size_t)b * NN * CC;
    for (int n0 = 0; n0 < LR; n0 += 4) {
        u64 p2[4][4];
        #pragma unroll
        for (int r = 0; r < 4; ++r)
            #pragma unroll
            for (int g = 0; g < 4; ++g) p2[r][g] = 0ull;

        #pragma unroll
        for (int r = 0; r < 4; ++r) {
            const ulonglong2* xp =
                (const ulonglong2*)(xb + (size_t)(n_base + n0 + r)*CC + sidx*16);
            u64 xx[8];
            #pragma unroll
            for (int j = 0; j < 4; ++j) {
                ulonglong2 v = xp[j];
                xx[2*j]   = v.x;
                xx[2*j+1] = v.y;
            }
            #pragma unroll
            for (int g = 0; g < 4; ++g)
                #pragma unroll
                for (int j = 0; j < 8; ++j)
                    ffma2(p2[r][g], xx[j], w2[g][j]);
        }

        // horizontal add + reduce across the 8 lanes sharing hg
        float p[4][4];
        #pragma unroll
        for (int r = 0; r < 4; ++r)
            #pragma unroll
            for (int g = 0; g < 4; ++g) {
                float lo, hi; unpack2(p2[r][g], lo, hi);
                float v = lo + hi;
                v += __shfl_xor_sync(0xffffffffu, v, 4);
                v += __shfl_xor_sync(0xffffffffu, v, 8);
                v += __shfl_xor_sync(0xffffffffu, v, 16);
                p[r][g] = v;
            }
        if (lane < 4) {
            #pragma unroll
            for (int r = 0; r < 4; ++r)
                #pragma unroll
                for (int g = 0; g < 4; ++g)
                    s_red[(r*8 + w)*16 + lane + 4*g] = p[r][g];
        }
        __syncthreads();
        if (t < 64) {
            int r = t >> 4, h = t & 15;
            float s = 0.f;
            #pragma unroll
            for (int ww = 0; ww < 8; ++ww) s += s_red[(r*8 + ww)*16 + h];
            g_att[((size_t)b*HH + h)*NN + n_base + n0 + r] = s;
        }
        __syncthreads();
    }
}

// ---------------------------------------------------------------------------
// Kernel 3: softmax over n per (b,h); exp in place + denom; zero g_xa.
// ---------------------------------------------------------------------------
__global__ void k_softmax() {
    int bh = blockIdx.x;              // 0..255
    int t  = threadIdx.x;             // 256
    float* row = g_att + (size_t)bh * NN;
    __shared__ float sred[256];

    for (int i = t; i < CC; i += 256) g_xa[(size_t)bh*CC + i] = 0.f;

    float m = -1e30f;
    for (int i = t; i < NN; i += 256) m = fmaxf(m, row[i]);
    sred[t] = m; __syncthreads();
    for (int s = 128; s > 0; s >>= 1) {
        if (t < s) sred[t] = fmaxf(sred[t], sred[t+s]);
        __syncthreads();
    }
    m = sred[0]; __syncthreads();

    float sum = 0.f;
    for (int i = t; i < NN; i += 256) {
        float e = __expf(row[i] - m);
        row[i] = e;
        sum += e;
    }
    sred[t] = sum; __syncthreads();
    for (int s = 128; s > 0; s >>= 1) {
        if (t < s) sred[t] += sred[t+s];
        __syncthreads();
    }
    if (t == 0) g_denom[bh] = sred[0];
}

// ---------------------------------------------------------------------------
// Kernel 4 (big pass 2): xa[b,h,c] += sum_n p[b,h,n] * x[b,n,c]
// Thread owns 4 contiguous c's x all 16 heads. Packed f32x2 accumulators:
// acc[hp][cj] = (head 2hp, head 2hp+1) at column c0+cj. Probs come out of
// smem already packed in head-pairs (LDS.128). Prefetch next x row.
// ---------------------------------------------------------------------------
#define XA_ROWS 64
__global__ void __launch_bounds__(256, 2) k_xa(const float* __restrict__ x) {
    int b      = blockIdx.y;
    int n_base = blockIdx.x * XA_ROWS;
    int t      = threadIdx.x;

    __shared__ float ps[XA_ROWS * 16];   // [n_local][h]  (4 KB)
    {
        int h = t & 15, ng = t >> 4;     // ng 0..15 -> rows ng*4..ng*4+3
        const float* ar = g_att + ((size_t)b*HH + h)*NN + n_base + ng*4;
        float4 a4 = *(const float4*)ar;
        ps[(ng*4+0)*16 + h] = a4.x;
        ps[(ng*4+1)*16 + h] = a4.y;
        ps[(ng*4+2)*16 + h] = a4.z;
        ps[(ng*4+3)*16 + h] = a4.w;
    }
    __syncthreads();

    int c0 = t * 4;
    const float* xp = x + ((size_t)b*NN + n_base)*CC + c0;

    u64 acc[8][4];
    #pragma unroll
    for (int hp = 0; hp < 8; ++hp)
        #pragma unroll
        for (int cj = 0; cj < 4; ++cj) acc[hp][cj] = 0ull;

    float4 xv = *(const float4*)xp;
    #pragma unroll 4
    for (int nl = 0; nl < XA_ROWS; ++nl) {
        int nn = (nl + 1 < XA_ROWS) ? nl + 1 : nl;
        float4 xn = *(const float4*)(xp + (size_t)nn * CC);

        const ulonglong2* pr = (const ulonglong2*)(ps + nl*16);
        ulonglong2 q0 = pr[0], q1 = pr[1], q2 = pr[2], q3 = pr[3];
        u64 pp[8] = {q0.x, q0.y, q1.x, q1.y, q2.x, q2.y, q3.x, q3.y};

        u64 xx0 = pack2(xv.x, xv.x);
        u64 xx1 = pack2(xv.y, xv.y);
        u64 xx2 = pack2(xv.z, xv.z);
        u64 xx3 = pack2(xv.w, xv.w);

        #pragma unroll
        for (int hp = 0; hp < 8; ++hp) {
            ffma2(acc[hp][0], pp[hp], xx0);
            ffma2(acc[hp][1], pp[hp], xx1);
            ffma2(acc[hp][2], pp[hp], xx2);
            ffma2(acc[hp][3], pp[hp], xx3);
        }
        xv = xn;
    }

    #pragma unroll
    for (int hp = 0; hp < 8; ++hp) {
        float* d0 = g_xa + ((size_t)b*HH + 2*hp    )*CC + c0;
        float* d1 = g_xa + ((size_t)b*HH + 2*hp + 1)*CC + c0;
        #pragma unroll
        for (int cj = 0; cj < 4; ++cj) {
            float lo, hi; unpack2(acc[hp][cj], lo, hi);
            atomicAdd(d0 + cj, lo);
            atomicAdd(d1 + cj, hi);
        }
    }
}

// ---------------------------------------------------------------------------
// Kernel 5: cls[b,h,d] = (1/denom) * sum_c xa[b,h,c] * Wkv_v[c,h,d]
// Also seeds out with bproj (k_proj atomic-adds on top).
// ---------------------------------------------------------------------------
__global__ void k_cls(const float* __restrict__ Wkv,
                      const float* __restrict__ bproj,
                      float* __restrict__ out) {
    int b = blockIdx.x >> 4, h = blockIdx.x & 15;
    int d = threadIdx.x;   // 64
    __shared__ float xas[CC];
    const float* xa = g_xa + ((size_t)b*HH + h)*CC;
    for (int c = d; c < CC; c += 64) xas[c] = xa[c];
    __syncthreads();

    const float* wv = Wkv + (HH*DD) + h*DD + d;   // v-half column offset 1024
    float acc = 0.f;
    #pragma unroll 8
    for (int c = 0; c < CC; ++c)
        acc += xas[c] * wv[(size_t)c * (2*HH*DD)];

    float inv = 1.0f / g_denom[b*HH + h];
    int col = h*DD + d;
    g_cls[(size_t)b*CC + col] = acc * inv;
    out[(size_t)b*CC + col]   = bproj[col];
}

// ---------------------------------------------------------------------------
// Kernel 6: out[b,j] += sum_i cls[b,i] * Wproj[i,j]
// ---------------------------------------------------------------------------
__global__ void k_proj(const float* __restrict__ Wproj,
                       float* __restrict__ out) {
    int jc = blockIdx.x;   // 0..3
    int ic = blockIdx.y;   // 0..3
    int b  = blockIdx.z;   // 0..15
    int tt = threadIdx.x;  // 256
    int j  = jc*256 + tt;

    __shared__ float cs[256];
    cs[tt] = g_cls[(size_t)b*CC + ic*256 + tt];
    __syncthreads();

    const float* wp = Wproj + (size_t)(ic*256) * CC + j;
    float acc = 0.f;
    #pragma unroll 8
    for (int i = 0; i < 256; ++i)
        acc += cs[i] * wp[(size_t)i * CC];
    atomicAdd(&out[(size_t)b*CC + j], acc);
}

// ---------------------------------------------------------------------------
extern "C" void kernel_launch(void* const* d_in, const int* in_sizes, int n_in,
                              void* d_out, int out_size) {
    const float* x     = (const float*)d_in[0];
    const float* Wq    = (const float*)d_in[1];
    const float* Wkv   = (const float*)d_in[2];
    const float* Wproj = (const float*)d_in[3];
    const float* bproj = (const float*)d_in[4];
    float* out = (float*)d_out;

    k_watt   <<<BB*HH, 256>>>(x, Wq, Wkv);
    k_logits <<<dim3(NN/LR, BB), 256>>>(x);
    k_softmax<<<BB*HH, 256>>>();
    k_xa     <<<dim3(NN/XA_ROWS, BB), 256>>>(x);
    k_cls    <<<BB*HH, 64>>>(Wkv, bproj, out);
    k_proj   <<<dim3(4, 4, BB), 256>>>(Wproj, out);
}